// round 9
// baseline (speedup 1.0000x reference)
#include <cuda_runtime.h>
#include <cuda_bf16.h>

// GCNet cost-volume + softargmax, specialized:
//   B=1, C=32, H=128, W=256, dmin=min_disp/2, dmax=max_disp/2 (default 0,64)
//
//   channels [0,C):   softmax over d-constant vector -> uniform -> mean disparity
//   channels [C,2C):  sliding-window softargmax over feaR.
//
// R1: fp64 -> fp32: 105 -> 10.7us (FP64-pipe-bound).
// R4: warp-per-row + smem windows: 10.7 -> 8.9us.
// R5: shfl windows + grid rebalance (1024 blocks): 8.9 -> 6.6us.
// R6: sliding-8 diff-only scan: issue count down, duration FLAT ->
//     kernel is latency-exposure bound (4096 warps total, issue 44%).
// R7: 2 rows per warp (64-thr blocks, 4 rows/block, grid stays 1024):
//     doubles MLP (4 outstanding LDG.128) and gives every latency chain
//     (exp, serial scan, shfl tree) an independent twin to interleave with.
// R8: resubmission — R7 bench never ran (GPU broker timeout).

#define GC_C 32
#define GC_H 128
#define GC_W 256
#define RPW  2                  // rows per warp
#define WPB  2                  // warps per block
#define ROWS_PER_BLOCK (RPW * WPB)
#define SPAD 292                // generic-fallback padded row

__device__ __forceinline__ int pad_idx(int i) { return i + (i >> 3); }

__global__ __launch_bounds__(32 * WPB)
void gcnet_softargmax_kernel(const float* __restrict__ feaR,
                             const int* __restrict__ p_min_disp,
                             const int* __restrict__ p_max_disp,
                             float* __restrict__ out)
{
    __shared__ float sP[ROWS_PER_BLOCK][SPAD];   // generic fallback only
    __shared__ float sQ[ROWS_PER_BLOCK][SPAD];

    const int lane  = threadIdx.x & 31;
    const int wrp   = threadIdx.x >> 5;
    const int row0  = blockIdx.x * ROWS_PER_BLOCK + wrp * RPW;  // two adjacent rows
    const int wbase = lane * 8;

    // ---- fire all 4 independent 16B loads immediately (MLP=4)
    const float* rp0 = feaR + (size_t)row0 * GC_W + wbase;
    const float* rp1 = rp0 + GC_W;
    const float4 a0 = *(const float4*)(rp0);
    const float4 a1 = *(const float4*)(rp0 + 4);
    const float4 b0 = *(const float4*)(rp1);
    const float4 b1 = *(const float4*)(rp1 + 4);

    const int min_disp = p_min_disp ? *p_min_disp : 0;
    const int max_disp = p_max_disp ? *p_max_disp : 128;
    const int dmin = min_disp / 2;
    const int dmax = max_disp / 2;
    const int D    = dmax - dmin;
    const float meanD    = 0.5f * (float)(dmin + dmax - 1);
    const float sumAll_d = meanD * (float)D;

    // ---- left channels: constant; fire these stores before compute
    float* outL0 = out + (size_t)row0 * GC_W + wbase;
    float* outL1 = outL0 + GC_W;
    const float4 cst = make_float4(meanD, meanD, meanD, meanD);
    *(float4*)(outL0)     = cst;
    *(float4*)(outL0 + 4) = cst;
    *(float4*)(outL1)     = cst;
    *(float4*)(outL1 + 4) = cst;

    // ---- exp + weighted values, two independent rows interleaved
    float e[RPW][8], q[RPW][8];
    {
        const float xs0[8] = { a0.x, a0.y, a0.z, a0.w, a1.x, a1.y, a1.z, a1.w };
        const float xs1[8] = { b0.x, b0.y, b0.z, b0.w, b1.x, b1.y, b1.z, b1.w };
        const float fw = (float)wbase;
        #pragma unroll
        for (int i = 0; i < 8; i++) {
            e[0][i] = __expf(xs0[i]);
            e[1][i] = __expf(xs1[i]);
            q[0][i] = (fw + (float)i) * e[0][i];
            q[1][i] = (fw + (float)i) * e[1][i];
        }
    }

    // ---- in-lane serial inclusive scans (independent chains interleave)
    #pragma unroll
    for (int i = 1; i < 8; i++) {
        e[0][i] += e[0][i - 1];  q[0][i] += q[0][i - 1];
        e[1][i] += e[1][i - 1];  q[1][i] += q[1][i - 1];
    }

    float res[RPW][8];

    if (dmin == 0 && D == 64) {
        // ===== fast path: only window differences needed.
        // slide-8 clamped sums of lane totals, both rows interleaved
        float ae0 = e[0][7], aq0 = q[0][7];
        float ae1 = e[1][7], aq1 = q[1][7];
        #pragma unroll
        for (int off = 1; off <= 4; off <<= 1) {
            const float t0 = __shfl_up_sync(0xffffffffu, ae0, off);
            const float u0 = __shfl_up_sync(0xffffffffu, aq0, off);
            const float t1 = __shfl_up_sync(0xffffffffu, ae1, off);
            const float u1 = __shfl_up_sync(0xffffffffu, aq1, off);
            if (lane >= off) { ae0 += t0; aq0 += u0; ae1 += t1; aq1 += u1; }
        }
        const float bde0u = __shfl_up_sync(0xffffffffu, ae0, 1);
        const float bdq0u = __shfl_up_sync(0xffffffffu, aq0, 1);
        const float bde1u = __shfl_up_sync(0xffffffffu, ae1, 1);
        const float bdq1u = __shfl_up_sync(0xffffffffu, aq1, 1);
        const bool  ln1 = (lane >= 1);
        const float bde[RPW] = { ln1 ? bde0u : 0.0f, ln1 ? bde1u : 0.0f };
        const float bdq[RPW] = { ln1 ? bdq0u : 0.0f, ln1 ? bdq1u : 0.0f };

        const float fw = (float)wbase;
        #pragma unroll
        for (int i = 0; i < 8; i++) {
            const float fwi  = fw + (float)i;
            const float fm   = fminf(63.0f, fwi);
            const float fInv = 63.0f - fm;
            const float corr = 2016.0f - 0.5f * fm * (fm + 1.0f);
            #pragma unroll
            for (int r = 0; r < RPW; r++) {
                const float pbu = __shfl_up_sync(0xffffffffu, e[r][i], 8);
                const float qbu = __shfl_up_sync(0xffffffffu, q[r][i], 8);
                const float pb  = (lane >= 8) ? pbu : 0.0f;
                const float qb  = (lane >= 8) ? qbu : 0.0f;
                const float dP = bde[r] + e[r][i] - pb;
                const float dQ = bdq[r] + q[r][i] - qb;
                const float s0 = dP + fInv;
                const float s1 = fwi * dP - dQ + corr;
                res[r][i] = __fdividef(s1, s0);
            }
        }
    } else {
        // ===== generic fallback (arbitrary dmin/dmax): absolute prefixes + smem
        #pragma unroll
        for (int r = 0; r < RPW; r++) {
            const int srow = wrp * RPW + r;
            float se = e[r][7], sq = q[r][7];
            const float tot_e = se, tot_q = sq;
            #pragma unroll
            for (int off = 1; off < 32; off <<= 1) {
                const float te = __shfl_up_sync(0xffffffffu, se, off);
                const float tq = __shfl_up_sync(0xffffffffu, sq, off);
                if (lane >= off) { se += te; sq += tq; }
            }
            const float base_e = se - tot_e;
            const float base_q = sq - tot_q;
            #pragma unroll
            for (int i = 0; i < 8; i++) {
                const int pi = pad_idx(wbase + i);
                sP[srow][pi] = e[r][i] + base_e;
                sQ[srow][pi] = q[r][i] + base_q;
            }
            __syncwarp();
            #pragma unroll
            for (int i = 0; i < 8; i++) {
                const int w = wbase + i;
                const int m = min(dmax - 1, w);
                if (m < dmin) {
                    res[r][i] = meanD;   // no valid disparity: uniform -> mean
                } else {
                    const int hi = w - dmin;
                    const int lo = w - m;
                    const float ph = sP[srow][pad_idx(hi)];
                    const float qh = sQ[srow][pad_idx(hi)];
                    float pb = 0.0f, qb = 0.0f;
                    if (lo > 0) {
                        const int bi = pad_idx(lo - 1);
                        pb = sP[srow][bi];
                        qb = sQ[srow][bi];
                    }
                    const float dP = ph - pb;
                    const float dQ = qh - qb;
                    const int   nValid = m - dmin + 1;
                    const int   nInv   = D - nValid;
                    const float sumValid_d = 0.5f * (float)(m + dmin) * (float)nValid;
                    const float s0 = dP + (float)nInv;
                    const float s1 = (float)w * dP - dQ + (sumAll_d - sumValid_d);
                    res[r][i] = __fdividef(s1, s0);
                }
            }
        }
    }

    // ---- right-channel stores
    float* outR0 = outL0 + (size_t)GC_C * GC_H * GC_W;
    float* outR1 = outR0 + GC_W;
    *(float4*)(outR0)     = make_float4(res[0][0], res[0][1], res[0][2], res[0][3]);
    *(float4*)(outR0 + 4) = make_float4(res[0][4], res[0][5], res[0][6], res[0][7]);
    *(float4*)(outR1)     = make_float4(res[1][0], res[1][1], res[1][2], res[1][3]);
    *(float4*)(outR1 + 4) = make_float4(res[1][4], res[1][5], res[1][6], res[1][7]);
}

extern "C" void kernel_launch(void* const* d_in, const int* in_sizes, int n_in,
                              void* d_out, int out_size)
{
    // metadata order: feaL (unused — left channels are constant), feaR, min_disp, max_disp
    const float* feaR = (const float*)d_in[1];
    const int* pmin = (n_in > 2) ? (const int*)d_in[2] : nullptr;
    const int* pmax = (n_in > 3) ? (const int*)d_in[3] : nullptr;
    float* out = (float*)d_out;

    dim3 grid((GC_C * GC_H) / ROWS_PER_BLOCK);   // 1024 blocks, 4 rows each
    dim3 block(32 * WPB);                         // 64 threads, 2 warps
    gcnet_softargmax_kernel<<<grid, block>>>(feaR, pmin, pmax, out);
}

// round 13
// speedup vs baseline: 1.0036x; 1.0036x over previous
#include <cuda_runtime.h>
#include <cuda_bf16.h>

// GCNet cost-volume + softargmax, specialized:
//   B=1, C=32, H=128, W=256, dmin=min_disp/2, dmax=max_disp/2 (default 0,64)
//
//   channels [0,C):   softmax over d-constant vector -> uniform -> mean disparity
//   channels [C,2C):  sliding-window softargmax over feaR.
//
// R1: fp64 -> fp32: 105 -> 10.7us (FP64-pipe-bound).
// R4: warp-per-row + smem windows: 10.7 -> 8.9us.
// R5: shfl windows + 1024-block grid: 8.9 -> 6.6us (kernel 5.92).
// R6: sliding-8 diff-only scan: flat (5.79) -> latency-exposure bound.
// R7: 2 rows/warp: REGRESSION (6.66, occ 16.7%) -> TLP beats ILP here.
// R9: half-row per warp (4 elems/lane, 2 warps/row) -> 8192 warps, ~55/SM:
//     - half 0: windows fully in-warp (clamp for lanes<16 == w<64,
//       shfl_up 16 for lanes>=16)
//     - half 1: lanes>=16 in-warp shfl; lanes<16 read half-0's prefixes
//       for elements 64..127 from smem (pad e+(e>>2): stride-4 conflict-free)
//     - one __syncthreads; grid stays 1024 blocks (256 thr, 4 rows/block)
// R10-R12: resubmissions — benches never ran (GPU broker timeouts).

#define GC_C 32
#define GC_H 128
#define GC_W 256
#define RPB  4                   // rows per block
#define SROW 324                 // 256 elements + stride-4 padding

__device__ __forceinline__ int pad4(int i) { return i + (i >> 2); }

__global__ __launch_bounds__(256)
void gcnet_softargmax_kernel(const float* __restrict__ feaR,
                             const int* __restrict__ p_min_disp,
                             const int* __restrict__ p_max_disp,
                             float* __restrict__ out)
{
    __shared__ float sP[RPB][SROW];
    __shared__ float sQ[RPB][SROW];
    __shared__ float sT[RPB][2];      // half-0 totals (P, Q) per row

    const int lane = threadIdx.x & 31;
    const int wid  = threadIdx.x >> 5;     // 0..7
    const int rloc = wid >> 1;             // row within block 0..3
    const int half = wid & 1;              // which 128-wide half of the row
    const int row  = blockIdx.x * RPB + rloc;       // row = c*H + h
    const int wbase = half * 128 + lane * 4;        // global w of slot 0

    // ---- load 4 elements (one float4) immediately
    const float4 v = *(const float4*)(feaR + (size_t)row * GC_W + wbase);

    const int min_disp = p_min_disp ? *p_min_disp : 0;
    const int max_disp = p_max_disp ? *p_max_disp : 128;
    const int dmin = min_disp / 2;
    const int dmax = max_disp / 2;
    const int D    = dmax - dmin;
    const float meanD    = 0.5f * (float)(dmin + dmax - 1);
    const float sumAll_d = meanD * (float)D;

    // ---- left channels: constant, store before compute
    float* outL = out + (size_t)row * GC_W + wbase;
    *(float4*)(outL) = make_float4(meanD, meanD, meanD, meanD);

    // ---- exp + weighted values
    const float xs[4] = { v.x, v.y, v.z, v.w };
    const float fw = (float)wbase;
    float e[4], q[4];
    #pragma unroll
    for (int i = 0; i < 4; i++) {
        e[i] = __expf(xs[i]);
        q[i] = (fw + (float)i) * e[i];
    }
    // in-lane serial inclusive scan
    #pragma unroll
    for (int i = 1; i < 4; i++) { e[i] += e[i - 1]; q[i] += q[i - 1]; }

    // warp scan of lane totals -> local (half-row) inclusive prefixes Pl/Ql
    float se = e[3], sq = q[3];
    const float tot_e = se, tot_q = sq;
    #pragma unroll
    for (int off = 1; off < 32; off <<= 1) {
        const float te = __shfl_up_sync(0xffffffffu, se, off);
        const float tq = __shfl_up_sync(0xffffffffu, sq, off);
        if (lane >= off) { se += te; sq += tq; }
    }
    const float base_e = se - tot_e;
    const float base_q = sq - tot_q;
    float Pl[4], Ql[4];
    #pragma unroll
    for (int i = 0; i < 4; i++) { Pl[i] = e[i] + base_e; Ql[i] = q[i] + base_q; }

    float res[4];

    if (dmin == 0 && D == 64) {
        // ===== fast path =====
        // half 0 publishes prefixes for elements 64..127 (its lanes 16..31)
        if (half == 0 && lane >= 16) {
            #pragma unroll
            for (int i = 0; i < 4; i++) {
                const int pe = pad4(wbase + i);
                sP[rloc][pe] = Pl[i];
                sQ[rloc][pe] = Ql[i];
            }
            if (lane == 31) { sT[rloc][0] = Pl[3]; sT[rloc][1] = Ql[3]; }
        }
        __syncthreads();

        if (half == 0) {
            #pragma unroll
            for (int i = 0; i < 4; i++) {
                const float fwi = fw + (float)i;
                const float pbu = __shfl_up_sync(0xffffffffu, Pl[i], 16);
                const float qbu = __shfl_up_sync(0xffffffffu, Ql[i], 16);
                const float pb  = (lane >= 16) ? pbu : 0.0f;  // lane<16 <=> w<64
                const float qb  = (lane >= 16) ? qbu : 0.0f;
                const float dP = Pl[i] - pb;
                const float dQ = Ql[i] - qb;
                const float fm   = fminf(63.0f, fwi);
                const float fInv = 63.0f - fm;
                const float corr = 2016.0f - 0.5f * fm * (fm + 1.0f);
                const float s0 = dP + fInv;
                const float s1 = fwi * dP - dQ + corr;
                res[i] = __fdividef(s1, s0);
            }
        } else {
            const float T0 = sT[rloc][0];
            const float U0 = sT[rloc][1];
            #pragma unroll
            for (int i = 0; i < 4; i++) {
                const float fwi = fw + (float)i;
                const float pbu = __shfl_up_sync(0xffffffffu, Pl[i], 16);
                const float qbu = __shfl_up_sync(0xffffffffu, Ql[i], 16);
                float dP, dQ;
                if (lane >= 16) {
                    dP = Pl[i] - pbu;            // T0 cancels in the difference
                    dQ = Ql[i] - qbu;
                } else {
                    const int be = pad4(wbase + i - 64);   // element 64..127
                    dP = T0 + Pl[i] - sP[rloc][be];
                    dQ = U0 + Ql[i] - sQ[rloc][be];
                }
                // w >= 128: full window, no invalid entries
                const float s1 = fwi * dP - dQ;
                res[i] = __fdividef(s1, dP);
            }
        }
    } else {
        // ===== generic fallback (arbitrary dmin/dmax) =====
        // every warp publishes LOCAL prefixes at absolute element index;
        // absolute prefix = stored + (e>=128 ? half0 total : 0)
        #pragma unroll
        for (int i = 0; i < 4; i++) {
            const int pe = pad4(wbase + i);
            sP[rloc][pe] = Pl[i];
            sQ[rloc][pe] = Ql[i];
        }
        if (half == 0 && lane == 31) { sT[rloc][0] = Pl[3]; sT[rloc][1] = Ql[3]; }
        __syncthreads();

        const float T0 = sT[rloc][0];
        const float U0 = sT[rloc][1];
        #pragma unroll
        for (int i = 0; i < 4; i++) {
            const int w = wbase + i;
            const int m = min(dmax - 1, w);
            if (m < dmin) {
                res[i] = meanD;      // no valid disparity: uniform -> mean
            } else {
                const int hi = w - dmin;
                const int lo = w - m;
                float ph = sP[rloc][pad4(hi)] + ((hi >= 128) ? T0 : 0.0f);
                float qh = sQ[rloc][pad4(hi)] + ((hi >= 128) ? U0 : 0.0f);
                float pb = 0.0f, qb = 0.0f;
                if (lo > 0) {
                    const int b = lo - 1;
                    pb = sP[rloc][pad4(b)] + ((b >= 128) ? T0 : 0.0f);
                    qb = sQ[rloc][pad4(b)] + ((b >= 128) ? U0 : 0.0f);
                }
                const float dP = ph - pb;
                const float dQ = qh - qb;
                const int   nValid = m - dmin + 1;
                const int   nInv   = D - nValid;
                const float sumValid_d = 0.5f * (float)(m + dmin) * (float)nValid;
                const float s0 = dP + (float)nInv;
                const float s1 = (float)w * dP - dQ + (sumAll_d - sumValid_d);
                res[i] = __fdividef(s1, s0);
            }
        }
    }

    // ---- right-channel store
    float* outR = outL + (size_t)GC_C * GC_H * GC_W;
    *(float4*)(outR) = make_float4(res[0], res[1], res[2], res[3]);
}

extern "C" void kernel_launch(void* const* d_in, const int* in_sizes, int n_in,
                              void* d_out, int out_size)
{
    // metadata order: feaL (unused — left channels are constant), feaR, min_disp, max_disp
    const float* feaR = (const float*)d_in[1];
    const int* pmin = (n_in > 2) ? (const int*)d_in[2] : nullptr;
    const int* pmax = (n_in > 3) ? (const int*)d_in[3] : nullptr;
    float* out = (float*)d_out;

    dim3 grid((GC_C * GC_H) / RPB);   // 1024 blocks, 4 rows each
    dim3 block(256);                   // 8 warps: 2 per row
    gcnet_softargmax_kernel<<<grid, block>>>(feaR, pmin, pmax, out);
}

// round 15
// speedup vs baseline: 1.2963x; 1.2917x over previous
#include <cuda_runtime.h>
#include <cuda_bf16.h>

// GCNet cost-volume + softargmax, specialized:
//   B=1, C=32, H=128, W=256, dmin=min_disp/2, dmax=max_disp/2 (default 0,64)
//
//   channels [0,C):   softmax over d-constant vector -> uniform -> mean disparity
//   channels [C,2C):  sliding-window softargmax over feaR.
//
// Optimization history (dur_us, graph-replay):
// R1: fp64 -> fp32: 105 -> 10.7us (FP64-pipe-bound).
// R4: warp-per-row + smem windows: 10.7 -> 8.9us.
// R5: shfl windows + 1024-block grid: 8.9 -> 6.62us.
// R6: sliding-8 diff-only scan (this kernel): 6.62us, kernel 5.79us.
// R7: 2 rows/warp (2048 warps): REGRESSION 8.96us, occ 16.7%.
// R9/R13: half-row/warp (8192 warps): occ 70%, issue 62% -- yet REGRESSION
//     8.93us. Bracketing complete: 4096-warp warp-per-row is optimal; duration
//     sits on a launch/ramp/overhead floor (~6.6us for this 12MB problem),
//     insensitive to both instruction count (R6 flat) and occupancy (R7/R9).
// R13 decision: revert to best measured kernel and FREEZE.
// R14: resubmission — R13 bench never ran (GPU broker timeout).

#define GC_C 32
#define GC_H 128
#define GC_W 256
#define RPB  4                  // rows per block (4 warps, one per SMSP)
#define SPAD 292                // generic-fallback padded row

__device__ __forceinline__ int pad_idx(int i) { return i + (i >> 3); }

__global__ __launch_bounds__(32 * RPB)
void gcnet_softargmax_kernel(const float* __restrict__ feaR,
                             const int* __restrict__ p_min_disp,
                             const int* __restrict__ p_max_disp,
                             float* __restrict__ out)
{
    __shared__ float sP[RPB][SPAD];   // generic fallback only
    __shared__ float sQ[RPB][SPAD];

    const int lane  = threadIdx.x & 31;
    const int wrp   = threadIdx.x >> 5;
    const int row   = blockIdx.x * RPB + wrp;      // row = c*H + h, 0..4095
    const int wbase = lane * 8;

    // ---- start the loads immediately
    const float* rptr = feaR + (size_t)row * GC_W + wbase;
    const float4 v0 = *(const float4*)(rptr);
    const float4 v1 = *(const float4*)(rptr + 4);

    const int min_disp = p_min_disp ? *p_min_disp : 0;
    const int max_disp = p_max_disp ? *p_max_disp : 128;
    const int dmin = min_disp / 2;
    const int dmax = max_disp / 2;
    const int D    = dmax - dmin;
    const float meanD    = 0.5f * (float)(dmin + dmax - 1);
    const float sumAll_d = meanD * (float)D;

    // ---- left channels: constant; fire these stores before compute
    float* outL = out + (size_t)row * GC_W + wbase;
    const float4 cst = make_float4(meanD, meanD, meanD, meanD);
    *(float4*)(outL)     = cst;
    *(float4*)(outL + 4) = cst;

    // ---- exp + weighted values
    const float xs[8] = { v0.x, v0.y, v0.z, v0.w, v1.x, v1.y, v1.z, v1.w };
    const float fw = (float)wbase;
    float e[8], q[8];
    #pragma unroll
    for (int i = 0; i < 8; i++) {
        e[i] = __expf(xs[i]);
        q[i] = (fw + (float)i) * e[i];
    }

    // ---- in-lane serial inclusive scan (local, no base)
    #pragma unroll
    for (int i = 1; i < 8; i++) { e[i] += e[i - 1]; q[i] += q[i - 1]; }

    const float tot_e = e[7], tot_q = q[7];
    float res[8];

    if (dmin == 0 && D == 64) {
        // ===== fast path: only window differences needed.
        // slide-8 clamped sums of lane totals: ae = sum tot[lane-7..lane]
        float ae = tot_e, aq = tot_q;
        #pragma unroll
        for (int off = 1; off <= 4; off <<= 1) {
            const float te = __shfl_up_sync(0xffffffffu, ae, off);
            const float tq = __shfl_up_sync(0xffffffffu, aq, off);
            if (lane >= off) { ae += te; aq += tq; }
        }
        // bdiff = sum tot[lane-8..lane-1] (clamped; ==exclusive prefix for lane<8)
        const float bdeu = __shfl_up_sync(0xffffffffu, ae, 1);
        const float bdqu = __shfl_up_sync(0xffffffffu, aq, 1);
        const float bde = (lane >= 1) ? bdeu : 0.0f;
        const float bdq = (lane >= 1) ? bdqu : 0.0f;

        #pragma unroll
        for (int i = 0; i < 8; i++) {
            const float fwi = fw + (float)i;
            const float pbu = __shfl_up_sync(0xffffffffu, e[i], 8);
            const float qbu = __shfl_up_sync(0xffffffffu, q[i], 8);
            const float pb  = (lane >= 8) ? pbu : 0.0f;
            const float qb  = (lane >= 8) ? qbu : 0.0f;
            const float dP = bde + e[i] - pb;
            const float dQ = bdq + q[i] - qb;
            // partial-window corrections; zero for w >= 63 (all lanes >= 8)
            const float fm   = fminf(63.0f, fwi);           // highest valid disparity
            const float fInv = 63.0f - fm;                  // invalid count (exp(0)=1)
            const float corr = 2016.0f - 0.5f * fm * (fm + 1.0f);
            const float s0 = dP + fInv;
            const float s1 = fwi * dP - dQ + corr;
            res[i] = __fdividef(s1, s0);
        }
    } else {
        // ===== generic fallback (arbitrary dmin/dmax): absolute prefixes + smem
        float se = tot_e, sq = tot_q;
        #pragma unroll
        for (int off = 1; off < 32; off <<= 1) {
            const float te = __shfl_up_sync(0xffffffffu, se, off);
            const float tq = __shfl_up_sync(0xffffffffu, sq, off);
            if (lane >= off) { se += te; sq += tq; }
        }
        const float base_e = se - tot_e;
        const float base_q = sq - tot_q;
        #pragma unroll
        for (int i = 0; i < 8; i++) {
            const int pi = pad_idx(wbase + i);
            sP[wrp][pi] = e[i] + base_e;
            sQ[wrp][pi] = q[i] + base_q;
        }
        __syncwarp();
        #pragma unroll
        for (int i = 0; i < 8; i++) {
            const int w = wbase + i;
            const int m = min(dmax - 1, w);
            if (m < dmin) {
                res[i] = meanD;      // no valid disparity: uniform -> mean
            } else {
                const int hi = w - dmin;
                const int lo = w - m;
                const float ph = sP[wrp][pad_idx(hi)];
                const float qh = sQ[wrp][pad_idx(hi)];
                float pb = 0.0f, qb = 0.0f;
                if (lo > 0) {
                    const int bi = pad_idx(lo - 1);
                    pb = sP[wrp][bi];
                    qb = sQ[wrp][bi];
                }
                const float dP = ph - pb;
                const float dQ = qh - qb;
                const int   nValid = m - dmin + 1;
                const int   nInv   = D - nValid;
                const float sumValid_d = 0.5f * (float)(m + dmin) * (float)nValid;
                const float s0 = dP + (float)nInv;
                const float s1 = (float)w * dP - dQ + (sumAll_d - sumValid_d);
                res[i] = __fdividef(s1, s0);
            }
        }
    }

    // ---- right-channel stores
    float* outR = outL + (size_t)GC_C * GC_H * GC_W;
    *(float4*)(outR)     = make_float4(res[0], res[1], res[2], res[3]);
    *(float4*)(outR + 4) = make_float4(res[4], res[5], res[6], res[7]);
}

extern "C" void kernel_launch(void* const* d_in, const int* in_sizes, int n_in,
                              void* d_out, int out_size)
{
    // metadata order: feaL (unused — left channels are constant), feaR, min_disp, max_disp
    const float* feaR = (const float*)d_in[1];
    const int* pmin = (n_in > 2) ? (const int*)d_in[2] : nullptr;
    const int* pmax = (n_in > 3) ? (const int*)d_in[3] : nullptr;
    float* out = (float*)d_out;

    dim3 grid((GC_C * GC_H) / RPB);   // 1024 blocks, 4 rows each
    dim3 block(32 * RPB);
    gcnet_softargmax_kernel<<<grid, block>>>(feaR, pmin, pmax, out);
}